// round 10
// baseline (speedup 1.0000x reference)
#include <cuda_runtime.h>
#include <cuda_bf16.h>
#include <math.h>

#define H 1024
#define W 1024
#define OROWS 8                      // output rows per CTA
#define HALO 4
#define SROWS (OROWS + 2 * HALO)     // 16 scan rows per CTA
#define SENT (1 << 30)

__device__ __forceinline__ float sqrt_approx(float x) {
    float r;
    asm("sqrt.approx.f32 %0, %1;" : "=f"(r) : "f"(x));
    return r;
}

// Exact fallback: brute force over all zero pixels. Correct for any input;
// probability of use ~2^-49 per pixel on this data (never fires).
__device__ __noinline__ float brute_force_d2(const float* __restrict__ img,
                                             int i, int j) {
    float best = 3.4e38f;
    for (int p = 0; p < H; p++) {
        const float dp = (float)(i - p);
        const float dp2 = dp * dp;
        if (dp2 >= best) continue;
        for (int q = 0; q < W; q++) {
            if (img[p * W + q] == 0.0f) {
                const float dq = (float)(j - q);
                best = fminf(best, dp2 + dq * dq);
            }
        }
    }
    if (best > 1e10f) best = 1e10f;  // no zero anywhere -> reference gives BIG
    return best;
}

// ---------------------------------------------------------------------------
// Fused EDT: phase A computes 16 row-scans (8 output + 4 halo each side) into
// 32KB smem as u16 distances; phase B does the +-4 parabola window per column.
// ---------------------------------------------------------------------------
__global__ void __launch_bounds__(1024) edt_fused_kernel(
    const float* __restrict__ img, float* __restrict__ out) {

    __shared__ unsigned short sd[SROWS][W];   // 32 KB row distances (clamped)
    __shared__ int sL[8][4], sR[8][4];        // per-iteration carry tables

    const int tid = threadIdx.x;
    const int lane = tid & 31;
    const int w = tid >> 5;
    const int rl = w >> 2;                    // 0..7: row within iteration
    const int quarter = w & 3;                // 0..3: quarter-row
    const int base = quarter * 256 + lane * 8;
    const int ob = blockIdx.x * OROWS;        // first output row of this CTA

    // ---------------- Phase A: row scans (2 iterations x 8 rows) ----------
    #pragma unroll
    for (int it = 0; it < 2; it++) {
        const int ridx = it * 8 + rl;         // scan-row 0..15
        const int srow = ob - HALO + ridx;    // global image row
        const bool valid = (srow >= 0) && (srow < H);

        unsigned mask = 0u;
        if (valid) {
            const float4* __restrict__ i4 =
                (const float4*)(img + srow * W) + base / 4;
            const float4 v0 = i4[0], v1 = i4[1];
            if (v0.x == 0.0f) mask |= 1u;
            if (v0.y == 0.0f) mask |= 2u;
            if (v0.z == 0.0f) mask |= 4u;
            if (v0.w == 0.0f) mask |= 8u;
            if (v1.x == 0.0f) mask |= 16u;
            if (v1.y == 0.0f) mask |= 32u;
            if (v1.z == 0.0f) mask |= 64u;
            if (v1.w == 0.0f) mask |= 128u;
        }

        const int aggL = mask ? (base + 31 - __clz(mask)) : -SENT;
        const int aggR = mask ? (base + __ffs(mask) - 1) : SENT;

        int a = aggL;
        #pragma unroll
        for (int o = 1; o < 32; o <<= 1) {
            int t = __shfl_up_sync(0xffffffffu, a, o);
            if (lane >= o) a = max(a, t);
        }
        int carryL = __shfl_up_sync(0xffffffffu, a, 1);
        if (lane == 0) carryL = -SENT;

        int b = aggR;
        #pragma unroll
        for (int o = 1; o < 32; o <<= 1) {
            int t = __shfl_down_sync(0xffffffffu, b, o);
            if (lane < 32 - o) b = min(b, t);
        }
        int carryR = __shfl_down_sync(0xffffffffu, b, 1);
        if (lane == 31) carryR = SENT;

        const int totL = __shfl_sync(0xffffffffu, a, 31);
        const int totR = __shfl_sync(0xffffffffu, b, 0);
        if (lane == 0) {
            sL[rl][quarter] = totL;
            sR[rl][quarter] = totR;
        }
        __syncthreads();
        #pragma unroll
        for (int q = 0; q < 4; q++) {
            if (q < quarter) carryL = max(carryL, sL[rl][q]);
            if (q > quarter) carryR = min(carryR, sR[rl][q]);
        }

        unsigned short dv[8];
        #pragma unroll
        for (int p = 0; p < 8; p++) {
            const int idx = base + p;
            const unsigned ml = mask & (0xFFu >> (7 - p));
            const unsigned mr = mask & (0xFFu << p);
            const int zl = ml ? (base + 31 - __clz(ml)) : carryL;
            const int zr = mr ? (base + __ffs(mr) - 1) : carryR;
            const int d = min(idx - zl, zr - idx);
            dv[p] = (unsigned short)min(d, 0xFFFF);   // sentinel clamp
        }

        uint4 pk;
        pk.x = (unsigned)dv[0] | ((unsigned)dv[1] << 16);
        pk.y = (unsigned)dv[2] | ((unsigned)dv[3] << 16);
        pk.z = (unsigned)dv[4] | ((unsigned)dv[5] << 16);
        pk.w = (unsigned)dv[6] | ((unsigned)dv[7] << 16);
        *(uint4*)(&sd[ridx][base]) = pk;

        __syncthreads();   // protects carry tables (WAR) and sd before phase B
    }

    // ---------------- Phase B: column parabola window ----------------------
    const int j = tid;   // one column per thread

    float win[SROWS];
    #pragma unroll
    for (int k = 0; k < SROWS; k++) win[k] = (float)sd[k][j];

    // Output u (row ob+u) centers at win[u + HALO].
    float m[OROWS];
    #pragma unroll
    for (int u = 0; u < OROWS; u++) {
        const float c = win[u + HALO];
        m[u] = c * c;
    }
    #pragma unroll
    for (int d = 1; d <= HALO; d++) {
        const float dd = (float)(d * d);
        #pragma unroll
        for (int u = 0; u < OROWS; u++) {
            const float a = win[u + HALO - d];
            const float b = win[u + HALO + d];
            m[u] = fminf(m[u], fmaf(a, a, dd));
            m[u] = fminf(m[u], fmaf(b, b, dd));
        }
    }

    // m <= 16 => exact (|i-k| >= 5 contributes >= 25 > 16). Else brute force.
    #pragma unroll
    for (int u = 0; u < OROWS; u++) {
        float mv = m[u];
        if (mv > 16.0f) mv = brute_force_d2(img, ob + u, j);
        out[(ob + u) * W + j] = sqrt_approx(mv);
    }
}

// ---------------------------------------------------------------------------
extern "C" void kernel_launch(void* const* d_in, const int* in_sizes, int n_in,
                              void* d_out, int out_size) {
    const float* img = (const float*)d_in[0];
    float* out = (float*)d_out;
    edt_fused_kernel<<<H / OROWS, 1024>>>(img, out);   // 128 CTAs
}